// round 1
// baseline (speedup 1.0000x reference)
#include <cuda_runtime.h>
#include <cstdint>

#define BB 32
#define TT 512
#define KK 48
#define KK2 2304            // K*K
#define NTH 384             // 8 x 48
#define START_TAG 46
#define STOP_TAG 47

__device__ float g_partials[BB];

__device__ __forceinline__ float ex2f(float x) {
    float y; asm("ex2.approx.ftz.f32 %0, %1;" : "=f"(y) : "f"(x)); return y;
}
__device__ __forceinline__ float lg2f(float x) {
    float y; asm("lg2.approx.ftz.f32 %0, %1;" : "=f"(y) : "f"(x)); return y;
}
__device__ __forceinline__ void cp16(uint32_t smem, const void* g) {
    asm volatile("cp.async.cg.shared.global [%0], [%1], 16;" :: "r"(smem), "l"(g));
}
__device__ __forceinline__ void cp_commit() {
    asm volatile("cp.async.commit_group;");
}
__device__ __forceinline__ void cp_wait1() {
    asm volatile("cp.async.wait_group 1;");
}

__global__ __launch_bounds__(NTH)
void crf_fwd_kernel(const float* __restrict__ feat,
                    const int*   __restrict__ targets,
                    const int*   __restrict__ lengths)
{
    __shared__ float tile[2][KK2];
    __shared__ float dsh[KK];       // c2[j] - c2[0]  (log2 domain, relative)
    __shared__ float red[8][KK];    // partial exp-sums per i-group
    __shared__ int   tsh[TT];
    __shared__ float refsh;         // absolute c2[0] (log2 domain)
    __shared__ float goldsh;

    const int b   = blockIdx.x;
    const int tid = threadIdx.x;
    const int len = lengths[b];
    const float* fb = feat + (size_t)b * TT * KK2;

    for (int i = tid; i < TT; i += NTH) tsh[i] = targets[b * TT + i];

    uint32_t s0 = (uint32_t)__cvta_generic_to_shared(&tile[0][0]);
    uint32_t s1 = (uint32_t)__cvta_generic_to_shared(&tile[1][0]);

    // Prologue: tile 0 (init + gold t=0), tile 1 (first step)
    for (int k = tid; k < KK2 / 4; k += NTH) cp16(s0 + k * 16, fb + k * 4);
    cp_commit();
    if (len > 1)
        for (int k = tid; k < KK2 / 4; k += NTH) cp16(s1 + k * 16, fb + KK2 + k * 4);
    cp_commit();
    cp_wait1();           // tile 0 ready
    __syncthreads();

    const float LOG2E = 1.4426950408889634f;
    const float LN2   = 0.6931471805599453f;

    if (tid < KK) {
        float v  = tile[0][START_TAG * KK + tid] * LOG2E;
        float v0 = tile[0][START_TAG * KK + 0]   * LOG2E;
        dsh[tid] = v - v0;
        if (tid == 0) { refsh = v0; goldsh = tile[0][tsh[0]]; }
    }
    // (visibility of dsh/refsh covered by the sync inside the first loop
    //  iteration; if len==1 we sync after the loop before reading them)

    const int j = tid % KK;
    const int r = tid / KK;

    for (int t = 1; t < len; ++t) {
        // Prefetch tile t+1 into the buffer holding tile t-1 (already consumed)
        uint32_t dst = (t & 1) ? s0 : s1;
        if (t + 1 < len) {
            const float* src = fb + (size_t)(t + 1) * KK2;
            for (int k = tid; k < KK2 / 4; k += NTH) cp16(dst + k * 16, src + k * 4);
        }
        cp_commit();
        cp_wait1();          // tile t ready (t+1 still in flight)
        __syncthreads();     // tile visible to all; dsh from previous step visible

        const float* ft = tile[t & 1];
        float acc = 0.f;
        #pragma unroll
        for (int ii = 0; ii < 6; ++ii) {
            int i = r + ii * 8;
            acc += ex2f(fmaf(ft[i * KK + j], LOG2E, dsh[i]));
        }
        red[r][j] = acc;
        if (tid == 0) goldsh += ft[tsh[t]];
        __syncthreads();

        if (tid < KK) {
            float s = 0.f, sz = 0.f;
            #pragma unroll
            for (int rr = 0; rr < 8; ++rr) { s += red[rr][tid]; sz += red[rr][0]; }
            float l  = lg2f(s);
            float l0 = lg2f(sz);
            dsh[tid] = l - l0;          // new relative carry
            if (tid == 0) refsh += l0;  // advance absolute offset
        }
        // next iteration's __syncthreads orders dsh writes vs. reads
    }

    __syncthreads();
    if (tid == 0) {
        float fin = (refsh + dsh[STOP_TAG]) * LN2;   // back to natural log
        g_partials[b] = fin - goldsh;
    }
}

__global__ void crf_reduce_kernel(float* __restrict__ out)
{
    float v = g_partials[threadIdx.x];
    #pragma unroll
    for (int o = 16; o; o >>= 1) v += __shfl_down_sync(0xffffffffu, v, o);
    if (threadIdx.x == 0) out[0] = v / (float)BB;
}

extern "C" void kernel_launch(void* const* d_in, const int* in_sizes, int n_in,
                              void* d_out, int out_size)
{
    const float* feat    = (const float*)d_in[0];
    const int*   targets = (const int*)d_in[1];
    const int*   lengths = (const int*)d_in[2];
    float*       out     = (float*)d_out;

    crf_fwd_kernel<<<BB, NTH>>>(feat, targets, lengths);
    crf_reduce_kernel<<<1, 32>>>(out);
}

// round 2
// speedup vs baseline: 1.3668x; 1.3668x over previous
#include <cuda_runtime.h>
#include <cstdint>

#define BB 32
#define TT 512
#define KK 48
#define SROW 52              // padded tile row stride in words (208 B, 16B-aligned)
#define NTH 384              // 12 warps
#define START_TAG 46
#define STOP_TAG 47
#define NCHUNK 576           // 48 rows * 12 chunks of 16B

__device__ float g_partials[BB];

__device__ __forceinline__ float ex2f(float x) {
    float y; asm("ex2.approx.ftz.f32 %0, %1;" : "=f"(y) : "f"(x)); return y;
}
__device__ __forceinline__ float lg2f(float x) {
    float y; asm("lg2.approx.ftz.f32 %0, %1;" : "=f"(y) : "f"(x)); return y;
}
__device__ __forceinline__ void cp16(uint32_t smem, const void* g) {
    asm volatile("cp.async.cg.shared.global [%0], [%1], 16;" :: "r"(smem), "l"(g));
}
__device__ __forceinline__ void cp_commit() {
    asm volatile("cp.async.commit_group;");
}
__device__ __forceinline__ void cp_wait1() {
    asm volatile("cp.async.wait_group 1;");
}
__device__ __forceinline__ void cp_wait2() {
    asm volatile("cp.async.wait_group 2;");
}

__global__ __launch_bounds__(NTH)
void crf_fwd_kernel(const float* __restrict__ feat,
                    const int*   __restrict__ targets,
                    const int*   __restrict__ lengths)
{
    __shared__ float tile[3][KK * SROW];   // 3 x 9984 B
    __shared__ float dsh[2][KK];           // double-buffered raw log2 carries
    __shared__ int   tsh[TT];              // padded target offsets

    const int b   = blockIdx.x;
    const int tid = threadIdx.x;
    const int len = lengths[b];
    const float* fb = feat + (size_t)b * TT * (KK * KK);

    // Preload targets as padded smem word offsets: (v/48)*SROW + v%48
    for (int i = tid; i < TT; i += NTH) {
        int v = targets[b * TT + i];
        tsh[i] = (v / KK) * SROW + (v % KK);
    }

    // thread mapping: warp w, lane l; column j = 4w + (l&3); i-group u = l>>2
    const int l = tid & 31;
    const int w = tid >> 5;
    const int j = 4 * w + (l & 3);
    const int u = l >> 2;

    // prefetch chunk offsets (constant per thread)
    const int k0 = tid;                 // always < NCHUNK
    const int k1 = tid + NTH;
    const bool has1 = (k1 < NCHUNK);
    const uint32_t so0 = (uint32_t)((k0 / 12) * SROW * 4 + (k0 % 12) * 16);
    const size_t   go0 = (size_t)(k0 / 12) * KK + (size_t)(k0 % 12) * 4;
    const uint32_t so1 = (uint32_t)((k1 / 12) * SROW * 4 + (k1 % 12) * 16);
    const size_t   go1 = (size_t)(k1 / 12) * KK + (size_t)(k1 % 12) * 4;

    uint32_t sbase[3];
    sbase[0] = (uint32_t)__cvta_generic_to_shared(&tile[0][0]);
    sbase[1] = (uint32_t)__cvta_generic_to_shared(&tile[1][0]);
    sbase[2] = (uint32_t)__cvta_generic_to_shared(&tile[2][0]);

    // Prologue: issue tiles 0,1,2 as three groups
    {
        cp16(sbase[0] + so0, fb + go0);
        if (has1) cp16(sbase[0] + so1, fb + go1);
        cp_commit();
        if (len > 1) {
            const float* src = fb + (size_t)1 * KK * KK;
            cp16(sbase[1] + so0, src + go0);
            if (has1) cp16(sbase[1] + so1, src + go1);
        }
        cp_commit();
        if (len > 2) {
            const float* src = fb + (size_t)2 * KK * KK;
            cp16(sbase[2] + so0, src + go0);
            if (has1) cp16(sbase[2] + so1, src + go1);
        }
        cp_commit();
    }
    cp_wait2();            // tile 0 ready
    __syncthreads();

    const float LOG2E = 1.4426950408889634f;
    const float LN2   = 0.6931471805599453f;

    // init raw carries (log2 domain, unnormalized) into dsh[1]
    if (tid < KK) dsh[1][tid] = tile[0][SROW * START_TAG + tid] * LOG2E;
    float gold  = 0.f;
    float refsh = 0.f;
    if (tid == 0) gold = tile[0][tsh[0]];

    for (int t = 1; t < len; ++t) {
        cp_wait1();          // tile t ready (tile t+1 still in flight)
        __syncthreads();     // dsh[t&1] + tile t visible; prior readers drained

        // prefetch tile t+2 into buffer (t+2)%3 (last read at iter t-1)
        if (t + 2 < len) {
            const float* src = fb + (size_t)(t + 2) * (KK * KK);
            uint32_t dst = sbase[(t + 2) % 3];
            cp16(dst + so0, src + go0);
            if (has1) cp16(dst + so1, src + go1);
        }
        cp_commit();

        const float* ft = tile[t % 3];
        const float* dr = dsh[t & 1];
        const float  d0 = dr[0];
        if (tid == 0) { refsh += d0; gold += ft[tsh[t]]; }

        const float* fcol = ft + (SROW * u + j);   // base for i = u + 8*ii
        float acc = 0.f;
        #pragma unroll
        for (int ii = 0; ii < 6; ++ii) {
            float rel = dr[u + 8 * ii] - d0;
            acc += ex2f(fmaf(fcol[SROW * 8 * ii], LOG2E, rel));
        }
        // reduce over u (lanes differing in bits 2..4)
        acc += __shfl_xor_sync(0xffffffffu, acc, 4);
        acc += __shfl_xor_sync(0xffffffffu, acc, 8);
        acc += __shfl_xor_sync(0xffffffffu, acc, 16);
        if (u == 0) dsh[(t + 1) & 1][j] = lg2f(acc);
        // next iteration's barrier orders these writes vs. reads
    }

    __syncthreads();
    if (tid == 0) {
        float fin = (refsh + dsh[len & 1][STOP_TAG]) * LN2;
        g_partials[b] = fin - gold;
    }
}

__global__ void crf_reduce_kernel(float* __restrict__ out)
{
    float v = g_partials[threadIdx.x];
    #pragma unroll
    for (int o = 16; o; o >>= 1) v += __shfl_down_sync(0xffffffffu, v, o);
    if (threadIdx.x == 0) out[0] = v / (float)BB;
}

extern "C" void kernel_launch(void* const* d_in, const int* in_sizes, int n_in,
                              void* d_out, int out_size)
{
    const float* feat    = (const float*)d_in[0];
    const int*   targets = (const int*)d_in[1];
    const int*   lengths = (const int*)d_in[2];
    float*       out     = (float*)d_out;

    crf_fwd_kernel<<<BB, NTH>>>(feat, targets, lengths);
    crf_reduce_kernel<<<1, 32>>>(out);
}

// round 3
// speedup vs baseline: 1.6045x; 1.1739x over previous
#include <cuda_runtime.h>
#include <cstdint>

#define BB 32
#define TT 512
#define KK 48
#define SROW 56              // padded row stride (224 B, 16B-aligned, conflict-free for u-stride)
#define NTH 192              // 6 warps
#define START_TAG 46
#define STOP_TAG 47
#define NCHUNK 576           // 48 rows * 12 chunks of 16 B

__device__ float g_partials[BB];
__device__ int   g_ctr = 0;

__device__ __forceinline__ float ex2f(float x) {
    float y; asm("ex2.approx.ftz.f32 %0, %1;" : "=f"(y) : "f"(x)); return y;
}
__device__ __forceinline__ float lg2f(float x) {
    float y; asm("lg2.approx.ftz.f32 %0, %1;" : "=f"(y) : "f"(x)); return y;
}
__device__ __forceinline__ void cp16(uint32_t smem, const void* g) {
    asm volatile("cp.async.cg.shared.global [%0], [%1], 16;" :: "r"(smem), "l"(g));
}
__device__ __forceinline__ void cp_commit() { asm volatile("cp.async.commit_group;"); }
__device__ __forceinline__ void cp_wait1()  { asm volatile("cp.async.wait_group 1;"); }
__device__ __forceinline__ void cp_wait2()  { asm volatile("cp.async.wait_group 2;"); }

// carry slot permutation: value for tag i lives at (i&3)*16 + (i>>2)
__device__ __forceinline__ int pslot(int i) { return (i & 3) * 16 + (i >> 2); }

__global__ __launch_bounds__(NTH)
void crf_fwd_kernel(const float* __restrict__ feat,
                    const int*   __restrict__ targets,
                    const int*   __restrict__ lengths,
                    float*       __restrict__ out)
{
    __shared__ __align__(16) float tile[3][KK * SROW];   // 3 x 10752 B
    __shared__ __align__(16) float dshP[2][64];          // permuted raw log2 carries
    __shared__ int tsh[TT];

    const int b   = blockIdx.x;
    const int tid = threadIdx.x;
    const int len = lengths[b];
    const float* fb = feat + (size_t)b * TT * (KK * KK);

    // targets -> padded smem word offsets
    for (int i = tid; i < TT; i += NTH) {
        int v = targets[b * TT + i];
        tsh[i] = (v / KK) * SROW + (v % KK);
    }

    // mapping: warp w, lane l. column j = 8w + (l&7); i = u + 4*ii, u = l>>3
    const int l = tid & 31;
    const int w = tid >> 5;
    const int j = 8 * w + (l & 7);
    const int u = l >> 3;

    // prefetch chunks: 3 per thread
    uint32_t so[3]; size_t go[3];
    #pragma unroll
    for (int q = 0; q < 3; ++q) {
        int k = tid + q * NTH;
        so[q] = (uint32_t)((k / 12) * SROW * 4 + (k % 12) * 16);
        go[q] = (size_t)(k / 12) * KK + (size_t)(k % 12) * 4;
    }

    uint32_t sbase[3];
    sbase[0] = (uint32_t)__cvta_generic_to_shared(&tile[0][0]);
    sbase[1] = (uint32_t)__cvta_generic_to_shared(&tile[1][0]);
    sbase[2] = (uint32_t)__cvta_generic_to_shared(&tile[2][0]);

    // Prologue: tiles 0,1,2 in three groups
    #pragma unroll
    for (int q = 0; q < 3; ++q) cp16(sbase[0] + so[q], fb + go[q]);
    cp_commit();
    if (len > 1) {
        const float* src = fb + (size_t)1 * KK * KK;
        #pragma unroll
        for (int q = 0; q < 3; ++q) cp16(sbase[1] + so[q], src + go[q]);
    }
    cp_commit();
    if (len > 2) {
        const float* src = fb + (size_t)2 * KK * KK;
        #pragma unroll
        for (int q = 0; q < 3; ++q) cp16(sbase[2] + so[q], src + go[q]);
    }
    cp_commit();
    cp_wait2();
    __syncthreads();

    const float LOG2E = 1.4426950408889634f;
    const float LN2   = 0.6931471805599453f;

    // init raw carries (log2, unnormalized) into buffer 1
    if (tid < KK) dshP[1][pslot(tid)] = tile[0][SROW * START_TAG + tid] * LOG2E;
    float gold  = 0.f;
    float refsh = 0.f;
    if (tid == 0) gold = tile[0][tsh[0]];

    for (int t = 1; t < len; ++t) {
        cp_wait1();
        __syncthreads();      // tile t + dshP[t&1] visible

        // prefetch tile t+2
        if (t + 2 < len) {
            const float* src = fb + (size_t)(t + 2) * (KK * KK);
            uint32_t dst = sbase[(t + 2) % 3];
            #pragma unroll
            for (int q = 0; q < 3; ++q) cp16(dst + so[q], src + go[q]);
        }
        cp_commit();

        const float* ft = tile[t % 3];
        const float* dr = dshP[t & 1];
        const float  d0 = dr[0];          // slot of tag 0 is 0
        if (tid == 0) { refsh += d0; gold += ft[tsh[t]]; }

        // 12 carries for this lane: tags u+4*ii live at dshP[u*16 + ii]
        float4 A = *(const float4*)(dr + u * 16 + 0);
        float4 B = *(const float4*)(dr + u * 16 + 4);
        float4 C = *(const float4*)(dr + u * 16 + 8);
        float rel[12] = {A.x,A.y,A.z,A.w, B.x,B.y,B.z,B.w, C.x,C.y,C.z,C.w};

        const float* fcol = ft + (u * SROW + j);   // i = u + 4*ii
        float acc0 = 0.f, acc1 = 0.f;
        #pragma unroll
        for (int ii = 0; ii < 12; ii += 2) {
            acc0 += ex2f(fmaf(fcol[SROW * 4 * ii],       LOG2E, rel[ii]     - d0));
            acc1 += ex2f(fmaf(fcol[SROW * 4 * (ii + 1)], LOG2E, rel[ii + 1] - d0));
        }
        float acc = acc0 + acc1;
        acc += __shfl_xor_sync(0xffffffffu, acc, 8);
        acc += __shfl_xor_sync(0xffffffffu, acc, 16);
        if (u == 0) dshP[(t + 1) & 1][pslot(j)] = lg2f(acc);
    }

    __syncthreads();
    if (tid == 0) {
        float fin = (refsh + dshP[len & 1][pslot(STOP_TAG)]) * LN2;
        g_partials[b] = fin - gold;
    }

    // last block reduces (deterministic fixed-order warp reduction)
    if (tid < 32) {
        int old = 0;
        if (tid == 0) {
            __threadfence();
            old = atomicAdd(&g_ctr, 1);
        }
        old = __shfl_sync(0xffffffffu, old, 0);
        if (old == BB - 1) {
            __threadfence();
            float v = g_partials[tid];
            #pragma unroll
            for (int o = 16; o; o >>= 1) v += __shfl_down_sync(0xffffffffu, v, o);
            if (tid == 0) { out[0] = v / (float)BB; g_ctr = 0; }
        }
    }
}

extern "C" void kernel_launch(void* const* d_in, const int* in_sizes, int n_in,
                              void* d_out, int out_size)
{
    const float* feat    = (const float*)d_in[0];
    const int*   targets = (const int*)d_in[1];
    const int*   lengths = (const int*)d_in[2];
    float*       out     = (float*)d_out;

    crf_fwd_kernel<<<BB, NTH>>>(feat, targets, lengths, out);
}